// round 10
// baseline (speedup 1.0000x reference)
#include <cuda_runtime.h>
#include <cuda_fp16.h>
#include <mma.h>
using namespace nvcuda;

#define M_NODES 1024
#define UPH 136           // half-row stride for uA/mT (272B, mult of 16B)
#define NTHREADS 256

__device__ float g_pe_i[M_NODES * 64];
__device__ float g_pe_jT[64 * M_NODES];   // transposed: [c][j]

// fast silu: 0.5v(1+tanh(v/2)) — single MUFU.TANH
__device__ __forceinline__ float silu_f(float v) {
    float hv = 0.5f * v, t;
    asm("tanh.approx.f32 %0, %1;" : "=f"(t) : "f"(hv));
    return fmaf(hv, t, hv);
}
// exact silu for the final phi_h layers (direct output path)
__device__ __forceinline__ float silu_x(float v) {
    return v / (1.0f + __expf(-v));
}

__global__ void pe_kernel(const float* __restrict__ h, const float* __restrict__ We1) {
    int id = blockIdx.x * blockDim.x + threadIdx.x;
    int i = id >> 6, k = id & 63;
    const float* hr = h + i * 64;
    float a0 = 0.f, a1 = 0.f;
#pragma unroll 8
    for (int c = 0; c < 64; c++) {
        float hv = hr[c];
        a0 += hv * We1[c * 64 + k];
        a1 += hv * We1[(64 + c) * 64 + k];
    }
    g_pe_i[id] = a0;
    g_pe_jT[k * M_NODES + i] = a1;
}

// SMEM layout (float offsets)
#define OFF_W2H   0         // 2048
#define OFF_WX1H  2048      // 2048
#define OFF_UA0   4096      // 4352
#define OFF_UA1   8448      // 4352
#define OFF_MTH   12800     // 4352
#define OFF_VEC   17152     // peib,w128,w129,wx2,be2,bx1 = 384
#define OFF_GEOA  17536     // 2*256 (d2+a)  (mis/gs alias at end)
#define OFF_REDXP 18048     // 4*132 = 528
#define OFF_SELF  18576     // u_self 64 + m_self 64
#define OFF_RED   18704     // redm 128 + redx 384
#define SMEM_FLOATS 19216
#define SMEM_BYTES (SMEM_FLOATS * 4)

// HMMA m16n16k16 fp32 accumulator mapping (sm_80+):
//   lane L: q=L>>2, p=L&3; element e: row = q + ((e&2)?8:0), col = 2p + (e&1) + ((e>=4)?8:0)

// GEMM B: mT = fp16(silu(W2^T @ u + be2)); per-row m_i partials in mi0 (row q), mi1 (row q+8).
__device__ __forceinline__ void gemmB(const __half* __restrict__ W2h,
                                      const __half* __restrict__ uAh,
                                      __half* __restrict__ mTh,
                                      const float* __restrict__ be2s,
                                      float& mi0, float& mi1,
                                      int kw, int jw, int lane)
{
    wmma::fragment<wmma::accumulator, 16, 16, 16, float> cf[4];
#pragma unroll
    for (int t = 0; t < 4; t++) wmma::fill_fragment(cf[t], 0.0f);
    wmma::fragment<wmma::matrix_a, 16, 16, 16, __half, wmma::col_major> af;
    wmma::fragment<wmma::matrix_b, 16, 16, 16, __half, wmma::row_major> bf;
#pragma unroll
    for (int c0 = 0; c0 < 64; c0 += 16) {
        wmma::load_matrix_sync(af, W2h + kw + c0 * 64, 64);
#pragma unroll
        for (int t = 0; t < 4; t++) {
            wmma::load_matrix_sync(bf, uAh + c0 * UPH + jw + 16 * t, UPH);
            wmma::mma_sync(cf[t], af, bf, cf[t]);
        }
    }
    const int q = lane >> 2, p = lane & 3;
    const int r0 = kw + q, r1 = r0 + 8;
    const float b0 = be2s[r0], b1 = be2s[r1];
#pragma unroll
    for (int t = 0; t < 4; t++) {
        float m0 = silu_f(cf[t].x[0] + b0), m1 = silu_f(cf[t].x[1] + b0);
        float m2 = silu_f(cf[t].x[2] + b1), m3 = silu_f(cf[t].x[3] + b1);
        float m4 = silu_f(cf[t].x[4] + b0), m5 = silu_f(cf[t].x[5] + b0);
        float m6 = silu_f(cf[t].x[6] + b1), m7 = silu_f(cf[t].x[7] + b1);
        mi0 += (m0 + m1) + (m4 + m5);
        mi1 += (m2 + m3) + (m6 + m7);
        __half2* d0 = (__half2*)(mTh + r0 * UPH + jw + 16 * t + p * 2);
        __half2* d1 = (__half2*)(mTh + r1 * UPH + jw + 16 * t + p * 2);
        d0[0] = __floats2half2_rn(m0, m1);
        d0[4] = __floats2half2_rn(m4, m5);
        d1[0] = __floats2half2_rn(m2, m3);
        d1[4] = __floats2half2_rn(m6, m7);
    }
}

// GEMM C: z = Wx1^T @ m; column-reduce silu(z+bx1)*wx2 over 16 k-rows -> redxp slice.
__device__ __forceinline__ void gemmC(const __half* __restrict__ Wx1h,
                                      const __half* __restrict__ mTh,
                                      const float* __restrict__ bx1s,
                                      const float* __restrict__ wx2s,
                                      float* __restrict__ redxp,
                                      int kw, int jw, int lane)
{
    wmma::fragment<wmma::accumulator, 16, 16, 16, float> cf[4];
#pragma unroll
    for (int t = 0; t < 4; t++) wmma::fill_fragment(cf[t], 0.0f);
    wmma::fragment<wmma::matrix_a, 16, 16, 16, __half, wmma::col_major> af;
    wmma::fragment<wmma::matrix_b, 16, 16, 16, __half, wmma::row_major> bf;
#pragma unroll
    for (int c0 = 0; c0 < 64; c0 += 16) {
        wmma::load_matrix_sync(af, Wx1h + kw + c0 * 64, 64);
#pragma unroll
        for (int t = 0; t < 4; t++) {
            wmma::load_matrix_sync(bf, mTh + c0 * UPH + jw + 16 * t, UPH);
            wmma::mma_sync(cf[t], af, bf, cf[t]);
        }
    }
    const int q = lane >> 2, p = lane & 3;
    const int r0 = kw + q, r1 = r0 + 8;
    const float ba = bx1s[r0], bb = bx1s[r1];
    const float wa = wx2s[r0], wb = wx2s[r1];
#pragma unroll
    for (int t = 0; t < 4; t++) {
        float s0 = silu_f(cf[t].x[0] + ba) * wa + silu_f(cf[t].x[2] + bb) * wb;
        float s1 = silu_f(cf[t].x[1] + ba) * wa + silu_f(cf[t].x[3] + bb) * wb;
        float s2 = silu_f(cf[t].x[4] + ba) * wa + silu_f(cf[t].x[6] + bb) * wb;
        float s3 = silu_f(cf[t].x[5] + ba) * wa + silu_f(cf[t].x[7] + bb) * wb;
#pragma unroll
        for (int msk = 4; msk <= 16; msk <<= 1) {
            s0 += __shfl_xor_sync(0xffffffff, s0, msk);
            s1 += __shfl_xor_sync(0xffffffff, s1, msk);
            s2 += __shfl_xor_sync(0xffffffff, s2, msk);
            s3 += __shfl_xor_sync(0xffffffff, s3, msk);
        }
        if (lane < 4) {
            float* rp = redxp + (kw >> 4) * 132 + jw + 16 * t + p * 2;
            *(float2*)rp       = make_float2(s0, s1);
            *(float2*)(rp + 8) = make_float2(s2, s3);
        }
    }
}

__global__ void __launch_bounds__(NTHREADS, 2) egnn_main(
    const float* __restrict__ x, const float* __restrict__ a,
    const float* __restrict__ h,
    const float* __restrict__ We1, const float* __restrict__ be1,
    const float* __restrict__ We2, const float* __restrict__ be2,
    const float* __restrict__ Wx1, const float* __restrict__ bx1,
    const float* __restrict__ Wx2, const float* __restrict__ bx2,
    const float* __restrict__ Wh1, const float* __restrict__ bh1,
    const float* __restrict__ Wh2, const float* __restrict__ bh2,
    float* __restrict__ out)
{
    extern __shared__ float sm[];
    __half* W2h  = (__half*)(sm + OFF_W2H);
    __half* Wx1h = (__half*)(sm + OFF_WX1H);
    __half* uA0h = (__half*)(sm + OFF_UA0);
    __half* uA1h = (__half*)(sm + OFF_UA1);
    __half* mTh  = (__half*)(sm + OFF_MTH);
    float* peib  = sm + OFF_VEC;
    float* w128s = peib + 64;
    float* w129s = w128s + 64;
    float* wx2s  = w129s + 64;
    float* be2s  = wx2s + 64;
    float* bx1s  = be2s + 64;
    float* redxp = sm + OFF_REDXP;
    float* u_self = sm + OFF_SELF;
    float* m_self = u_self + 64;

    const int tid = threadIdx.x;
    const int i = blockIdx.x;
    const int lane = tid & 31;
    const int w = tid >> 5;
    const int kw = (w & 3) * 16;
    const int jw = (w >> 2) * 64;

    for (int e = tid; e < 4096; e += NTHREADS) {
        W2h[e]  = __float2half_rn(We2[e]);
        Wx1h[e] = __float2half_rn(Wx1[e]);
    }
    if (tid < 64) {
        peib[tid]  = g_pe_i[i * 64 + tid] + be1[tid];
        w128s[tid] = We1[128 * 64 + tid];
        w129s[tid] = We1[129 * 64 + tid];
        wx2s[tid]  = Wx2[tid];
        be2s[tid]  = be2[tid];
        bx1s[tid]  = bx1[tid];
    }
    const float xi0 = x[i * 3 + 0], xi1 = x[i * 3 + 1], xi2 = x[i * 3 + 2];
    const float bx2v = bx2[0];

    // geoA[0] for tile 0
    if (tid < 128) {
        float* g0 = sm + OFF_GEOA;
        float dx = xi0 - x[tid * 3 + 0];
        float dy = xi1 - x[tid * 3 + 1];
        float dz = xi2 - x[tid * 3 + 2];
        g0[tid] = dx * dx + dy * dy + dz * dz;
        g0[128 + tid] = a[i * M_NODES + tid];
    }
    __syncthreads();

    // u_self (fp16-rounded, same tanh-silu as main path) + phase A for tile 0
    if (tid < 64) {
        float a_ii = a[i * M_NODES + i];
        float pre = peib[tid] + g_pe_jT[tid * M_NODES + i] + a_ii * w129s[tid];
        u_self[tid] = __half2float(__float2half_rn(silu_f(pre)));
    }
    {
        const float* geoA = sm + OFF_GEOA;
        const int jq = lane * 4;
#pragma unroll
        for (int p = 0; p < 8; p++) {
            int c = p * 8 + w;
            float4 pj = *(const float4*)&g_pe_jT[c * M_NODES + jq];
            float pc = peib[c], wa = w128s[c], wb = w129s[c];
            float4 dd = *(const float4*)&geoA[jq];
            float4 aa = *(const float4*)&geoA[128 + jq];
            __half hh[4];
            hh[0] = __float2half_rn(silu_f(pc + pj.x + dd.x * wa + aa.x * wb));
            hh[1] = __float2half_rn(silu_f(pc + pj.y + dd.y * wa + aa.y * wb));
            hh[2] = __float2half_rn(silu_f(pc + pj.z + dd.z * wa + aa.z * wb));
            hh[3] = __float2half_rn(silu_f(pc + pj.w + dd.w * wa + aa.w * wb));
            *(uint2*)(uA0h + c * UPH + jq) = *(uint2*)hh;
        }
    }
    __syncthreads();

    float mi0 = 0.f, mi1 = 0.f;
    float ax = 0.f, ay = 0.f, az = 0.f;

    for (int t = 0; t < 8; t++) {
        __half* uCur  = (t & 1) ? uA1h : uA0h;
        __half* uNext = (t & 1) ? uA0h : uA1h;

        // ======== Phase P1: GEMM B (+ m_self(t0), x-accum(t-1), geo prefetch) ========
        const bool pf = (tid < 128) && (t + 1 < 8);
        float pd2 = 0.f, pa = 0.f;
        if (pf) {
            int jn = (t + 1) * 128 + tid;
            float dx = xi0 - x[jn * 3 + 0];
            float dy = xi1 - x[jn * 3 + 1];
            float dz = xi2 - x[jn * 3 + 2];
            pd2 = dx * dx + dy * dy + dz * dz;
            pa = a[i * M_NODES + jn];
        }
        if (t == 0 && tid < 64) {
            float accd = be2s[tid];
#pragma unroll 8
            for (int c = 0; c < 64; c++)
                accd += u_self[c] * __half2float(W2h[tid + c * 64]);
            m_self[tid] = silu_f(accd);
        }
        if (t > 0 && tid < 128) {
            int jg = (t - 1) * 128 + tid;
            float s = bx2v + redxp[tid] + redxp[132 + tid]
                           + redxp[264 + tid] + redxp[396 + tid];
            float dx = xi0 - x[jg * 3 + 0];
            float dy = xi1 - x[jg * 3 + 1];
            float dz = xi2 - x[jg * 3 + 2];
            ax += dx * s; ay += dy * s; az += dz * s;
        }

        gemmB(W2h, uCur, mTh, be2s, mi0, mi1, kw, jw, lane);

        if (pf) {
            float* gn = sm + OFF_GEOA + ((t + 1) & 1) * 256;
            gn[tid] = pd2;
            gn[128 + tid] = pa;
        }
        __syncthreads();

        // ======== Phase P2: GEMM C + phase A(t+1) ========
        gemmC(Wx1h, mTh, bx1s, wx2s, redxp, kw, jw, lane);

        if (t + 1 < 8) {
            const float* geoA = sm + OFF_GEOA + ((t + 1) & 1) * 256;
            const int j0 = (t + 1) * 128;
            const int jq = lane * 4;
#pragma unroll
            for (int p = 0; p < 8; p++) {
                int c = p * 8 + w;
                float4 pj = *(const float4*)&g_pe_jT[c * M_NODES + j0 + jq];
                float pc = peib[c], wa = w128s[c], wb = w129s[c];
                float4 dd = *(const float4*)&geoA[jq];
                float4 aa = *(const float4*)&geoA[128 + jq];
                __half hh[4];
                hh[0] = __float2half_rn(silu_f(pc + pj.x + dd.x * wa + aa.x * wb));
                hh[1] = __float2half_rn(silu_f(pc + pj.y + dd.y * wa + aa.y * wb));
                hh[2] = __float2half_rn(silu_f(pc + pj.z + dd.z * wa + aa.z * wb));
                hh[3] = __float2half_rn(silu_f(pc + pj.w + dd.w * wa + aa.w * wb));
                *(uint2*)(uNext + c * UPH + jq) = *(uint2*)hh;
            }
        }
        __syncthreads();
    }

    // x-accum for tile 7
    if (tid < 128) {
        int jg = 7 * 128 + tid;
        float s = bx2v + redxp[tid] + redxp[132 + tid]
                       + redxp[264 + tid] + redxp[396 + tid];
        float dx = xi0 - x[jg * 3 + 0];
        float dy = xi1 - x[jg * 3 + 1];
        float dz = xi2 - x[jg * 3 + 2];
        ax += dx * s; ay += dy * s; az += dz * s;
    }

    // ---- m_i reduction: combine lanes sharing the same k-row (xor 1,2) ----
    mi0 += __shfl_xor_sync(0xffffffff, mi0, 1);
    mi0 += __shfl_xor_sync(0xffffffff, mi0, 2);
    mi1 += __shfl_xor_sync(0xffffffff, mi1, 1);
    mi1 += __shfl_xor_sync(0xffffffff, mi1, 2);

    float* redm = sm + OFF_RED;           // [64][2]
    float* redx = sm + OFF_RED + 128;     // 384
    {
        const int q = lane >> 2, g = jw >> 6;
        if ((lane & 3) == 0) {
            redm[(kw + q) * 2 + g]     = mi0;
            redm[(kw + q + 8) * 2 + g] = mi1;
        }
    }
    if (tid < 128) { redx[tid] = ax; redx[128 + tid] = ay; redx[256 + tid] = az; }
    __syncthreads();

    float* mis = sm + OFF_GEOA;
    float* gs  = sm + OFF_GEOA + 64;
    if (tid < 64) {
        mis[tid] = redm[tid * 2] + redm[tid * 2 + 1] - m_self[tid];
    }
    if (tid >= 128 && tid < 131) {
        int comp = tid - 128;
        float s = 0.f;
        for (int q = 0; q < 128; q++) s += redx[comp * 128 + q];
        const float C = 1.0f / (float)(M_NODES - 1);
        out[i * 3 + comp] = x[i * 3 + comp] + C * s;
    }
    __syncthreads();

    // phi_h (exact silu: direct output path)
    if (tid < 64) {
        float acc = bh1[tid];
        const float* hr = h + i * 64;
#pragma unroll 4
        for (int c = 0; c < 64; c++) acc += hr[c] * Wh1[c * 64 + tid];
#pragma unroll 4
        for (int c = 0; c < 64; c++) acc += mis[c] * Wh1[(64 + c) * 64 + tid];
        gs[tid] = silu_x(acc);
    }
    __syncthreads();
    if (tid < 64) {
        float acc = bh2[tid];
#pragma unroll 4
        for (int c = 0; c < 64; c++) acc += gs[c] * Wh2[c * 64 + tid];
        out[3 * M_NODES + i * 64 + tid] = acc;
    }
}

extern "C" void kernel_launch(void* const* d_in, const int* in_sizes, int n_in,
                              void* d_out, int out_size) {
    const float* x   = (const float*)d_in[0];
    const float* a   = (const float*)d_in[1];
    const float* h   = (const float*)d_in[2];
    const float* We1 = (const float*)d_in[3];
    const float* be1 = (const float*)d_in[4];
    const float* We2 = (const float*)d_in[5];
    const float* be2 = (const float*)d_in[6];
    const float* Wx1 = (const float*)d_in[7];
    const float* bx1 = (const float*)d_in[8];
    const float* Wx2 = (const float*)d_in[9];
    const float* bx2 = (const float*)d_in[10];
    const float* Wh1 = (const float*)d_in[11];
    const float* bh1 = (const float*)d_in[12];
    const float* Wh2 = (const float*)d_in[13];
    const float* bh2 = (const float*)d_in[14];
    float* out = (float*)d_out;

    cudaFuncSetAttribute(egnn_main, cudaFuncAttributeMaxDynamicSharedMemorySize, SMEM_BYTES);

    pe_kernel<<<(M_NODES * 64) / NTHREADS, NTHREADS>>>(h, We1);
    egnn_main<<<M_NODES, NTHREADS, SMEM_BYTES>>>(
        x, a, h, We1, be1, We2, be2, Wx1, bx1, Wx2, bx2,
        Wh1, bh1, Wh2, bh2, out);
}

// round 11
// speedup vs baseline: 1.2588x; 1.2588x over previous
#include <cuda_runtime.h>
#include <cuda_fp16.h>
#include <mma.h>
using namespace nvcuda;

#define M_NODES 1024
#define UPH 136           // half-row stride for uA/mT (272B, mult of 16B)
#define NTHREADS 256
#define NCTAS 296         // persistent: 2 per SM on 148 SMs, fully resident
#define NITEMS 2048       // (node i, j-half)

__device__ float g_pe_i[M_NODES * 64];
__device__ float g_pe_jT[64 * M_NODES];   // transposed: [c][j]
__device__ __half g_W2h[4096];
__device__ __half g_Wx1h[4096];
__device__ float g_mi[2][M_NODES][64];
__device__ float g_xp[2][M_NODES][4];

// fast silu: 0.5v(1+tanh(v/2)) — single MUFU.TANH
__device__ __forceinline__ float silu_f(float v) {
    float hv = 0.5f * v, t;
    asm("tanh.approx.f32 %0, %1;" : "=f"(t) : "f"(hv));
    return fmaf(hv, t, hv);
}
// exact silu for the final phi_h layer (direct output path)
__device__ __forceinline__ float silu_x(float v) {
    return v / (1.0f + __expf(-v));
}

__global__ void pe_kernel(const float* __restrict__ h, const float* __restrict__ We1,
                          const float* __restrict__ We2, const float* __restrict__ Wx1) {
    int id = blockIdx.x * blockDim.x + threadIdx.x;
    if (id < 4096) {
        g_W2h[id]  = __float2half_rn(We2[id]);
        g_Wx1h[id] = __float2half_rn(Wx1[id]);
    }
    int i = id >> 6, k = id & 63;
    const float* hr = h + i * 64;
    float a0 = 0.f, a1 = 0.f;
#pragma unroll 8
    for (int c = 0; c < 64; c++) {
        float hv = hr[c];
        a0 += hv * We1[c * 64 + k];
        a1 += hv * We1[(64 + c) * 64 + k];
    }
    g_pe_i[id] = a0;
    g_pe_jT[k * M_NODES + i] = a1;
}

// SMEM layout (float offsets)
#define OFF_W2H   0         // 2048
#define OFF_WX1H  2048      // 2048
#define OFF_UA0   4096      // 4352
#define OFF_UA1   8448      // 4352
#define OFF_MTH   12800     // 4352
#define OFF_VEC   17152     // peib,w128,w129,wx2,be2,bx1 = 384
#define OFF_GEOA  17536     // 2*256 (d2+a)
#define OFF_REDXP 18048     // 4*132 = 528
#define OFF_RED   18576     // redm 128 + redx 384
#define SMEM_FLOATS 19088
#define SMEM_BYTES (SMEM_FLOATS * 4)

// HMMA m16n16k16 fp32 accumulator mapping (sm_80+):
//   lane L: q=L>>2, p=L&3; element e: row = q + ((e&2)?8:0), col = 2p + (e&1) + ((e>=4)?8:0)

__device__ __forceinline__ void gemmB(const __half* __restrict__ W2h,
                                      const __half* __restrict__ uAh,
                                      __half* __restrict__ mTh,
                                      const float* __restrict__ be2s,
                                      float& mi0, float& mi1,
                                      int kw, int jw, int lane)
{
    wmma::fragment<wmma::accumulator, 16, 16, 16, float> cf[4];
#pragma unroll
    for (int t = 0; t < 4; t++) wmma::fill_fragment(cf[t], 0.0f);
    wmma::fragment<wmma::matrix_a, 16, 16, 16, __half, wmma::col_major> af;
    wmma::fragment<wmma::matrix_b, 16, 16, 16, __half, wmma::row_major> bf;
#pragma unroll
    for (int c0 = 0; c0 < 64; c0 += 16) {
        wmma::load_matrix_sync(af, W2h + kw + c0 * 64, 64);
#pragma unroll
        for (int t = 0; t < 4; t++) {
            wmma::load_matrix_sync(bf, uAh + c0 * UPH + jw + 16 * t, UPH);
            wmma::mma_sync(cf[t], af, bf, cf[t]);
        }
    }
    const int q = lane >> 2, p = lane & 3;
    const int r0 = kw + q, r1 = r0 + 8;
    const float b0 = be2s[r0], b1 = be2s[r1];
#pragma unroll
    for (int t = 0; t < 4; t++) {
        float m0 = silu_f(cf[t].x[0] + b0), m1 = silu_f(cf[t].x[1] + b0);
        float m2 = silu_f(cf[t].x[2] + b1), m3 = silu_f(cf[t].x[3] + b1);
        float m4 = silu_f(cf[t].x[4] + b0), m5 = silu_f(cf[t].x[5] + b0);
        float m6 = silu_f(cf[t].x[6] + b1), m7 = silu_f(cf[t].x[7] + b1);
        mi0 += (m0 + m1) + (m4 + m5);
        mi1 += (m2 + m3) + (m6 + m7);
        __half2* d0 = (__half2*)(mTh + r0 * UPH + jw + 16 * t + p * 2);
        __half2* d1 = (__half2*)(mTh + r1 * UPH + jw + 16 * t + p * 2);
        d0[0] = __floats2half2_rn(m0, m1);
        d0[4] = __floats2half2_rn(m4, m5);
        d1[0] = __floats2half2_rn(m2, m3);
        d1[4] = __floats2half2_rn(m6, m7);
    }
}

__device__ __forceinline__ void gemmC(const __half* __restrict__ Wx1h,
                                      const __half* __restrict__ mTh,
                                      const float* __restrict__ bx1s,
                                      const float* __restrict__ wx2s,
                                      float* __restrict__ redxp,
                                      int kw, int jw, int lane)
{
    wmma::fragment<wmma::accumulator, 16, 16, 16, float> cf[4];
#pragma unroll
    for (int t = 0; t < 4; t++) wmma::fill_fragment(cf[t], 0.0f);
    wmma::fragment<wmma::matrix_a, 16, 16, 16, __half, wmma::col_major> af;
    wmma::fragment<wmma::matrix_b, 16, 16, 16, __half, wmma::row_major> bf;
#pragma unroll
    for (int c0 = 0; c0 < 64; c0 += 16) {
        wmma::load_matrix_sync(af, Wx1h + kw + c0 * 64, 64);
#pragma unroll
        for (int t = 0; t < 4; t++) {
            wmma::load_matrix_sync(bf, mTh + c0 * UPH + jw + 16 * t, UPH);
            wmma::mma_sync(cf[t], af, bf, cf[t]);
        }
    }
    const int q = lane >> 2, p = lane & 3;
    const int r0 = kw + q, r1 = r0 + 8;
    const float ba = bx1s[r0], bb = bx1s[r1];
    const float wa = wx2s[r0], wb = wx2s[r1];
#pragma unroll
    for (int t = 0; t < 4; t++) {
        float s0 = silu_f(cf[t].x[0] + ba) * wa + silu_f(cf[t].x[2] + bb) * wb;
        float s1 = silu_f(cf[t].x[1] + ba) * wa + silu_f(cf[t].x[3] + bb) * wb;
        float s2 = silu_f(cf[t].x[4] + ba) * wa + silu_f(cf[t].x[6] + bb) * wb;
        float s3 = silu_f(cf[t].x[5] + ba) * wa + silu_f(cf[t].x[7] + bb) * wb;
#pragma unroll
        for (int msk = 4; msk <= 16; msk <<= 1) {
            s0 += __shfl_xor_sync(0xffffffff, s0, msk);
            s1 += __shfl_xor_sync(0xffffffff, s1, msk);
            s2 += __shfl_xor_sync(0xffffffff, s2, msk);
            s3 += __shfl_xor_sync(0xffffffff, s3, msk);
        }
        if (lane < 4) {
            float* rp = redxp + (kw >> 4) * 132 + jw + 16 * t + p * 2;
            *(float2*)rp       = make_float2(s0, s1);
            *(float2*)(rp + 8) = make_float2(s2, s3);
        }
    }
}

__global__ void __launch_bounds__(NTHREADS, 2) egnn_main(
    const float* __restrict__ x, const float* __restrict__ a,
    const float* __restrict__ We1, const float* __restrict__ be1,
    const float* __restrict__ be2, const float* __restrict__ bx1,
    const float* __restrict__ Wx2, const float* __restrict__ bx2)
{
    extern __shared__ float sm[];
    __half* W2h  = (__half*)(sm + OFF_W2H);
    __half* Wx1h = (__half*)(sm + OFF_WX1H);
    __half* uA0h = (__half*)(sm + OFF_UA0);
    __half* uA1h = (__half*)(sm + OFF_UA1);
    __half* mTh  = (__half*)(sm + OFF_MTH);
    float* peib  = sm + OFF_VEC;
    float* w128s = peib + 64;
    float* w129s = w128s + 64;
    float* wx2s  = w129s + 64;
    float* be2s  = wx2s + 64;
    float* bx1s  = be2s + 64;
    float* redxp = sm + OFF_REDXP;
    float* redm  = sm + OFF_RED;          // [64][2]
    float* redx  = sm + OFF_RED + 128;    // 384

    const int tid = threadIdx.x;
    const int lane = tid & 31;
    const int w = tid >> 5;
    const int kw = (w & 3) * 16;
    const int jw = (w >> 2) * 64;

    // ---- one-time prologue: weights + layer vectors ----
    {
        const uint4* s2 = (const uint4*)g_W2h;
        const uint4* sx = (const uint4*)g_Wx1h;
        uint4* d2 = (uint4*)W2h;
        uint4* dx = (uint4*)Wx1h;
#pragma unroll
        for (int e = tid; e < 512; e += NTHREADS) { d2[e] = s2[e]; dx[e] = sx[e]; }
    }
    if (tid < 64) {
        w128s[tid] = We1[128 * 64 + tid];
        w129s[tid] = We1[129 * 64 + tid];
        wx2s[tid]  = Wx2[tid];
        be2s[tid]  = be2[tid];
        bx1s[tid]  = bx1[tid];
    }
    const float bx2v = bx2[0];

    for (int it = blockIdx.x; it < NITEMS; it += NCTAS) {
        const int i = it >> 1;
        const int half = it & 1;
        const int jbase0 = half * 512;
        const float xi0 = x[i * 3 + 0], xi1 = x[i * 3 + 1], xi2 = x[i * 3 + 2];

        // per-item: peib + geometry for first tile
        if (tid < 64) peib[tid] = g_pe_i[i * 64 + tid] + be1[tid];
        if (tid < 128) {
            float* g0 = sm + OFF_GEOA;
            int jn = jbase0 + tid;
            float dx = xi0 - x[jn * 3 + 0];
            float dy = xi1 - x[jn * 3 + 1];
            float dz = xi2 - x[jn * 3 + 2];
            g0[tid] = dx * dx + dy * dy + dz * dz;
            g0[128 + tid] = a[i * M_NODES + jn];
        }
        __syncthreads();

        // initial phase A (tile 0 of this item)
        {
            const float* geoA = sm + OFF_GEOA;
            const int jq = lane * 4;
#pragma unroll
            for (int p = 0; p < 8; p++) {
                int c = p * 8 + w;
                float4 pj = *(const float4*)&g_pe_jT[c * M_NODES + jbase0 + jq];
                float pc = peib[c], wa = w128s[c], wb = w129s[c];
                float4 dd = *(const float4*)&geoA[jq];
                float4 aa = *(const float4*)&geoA[128 + jq];
                __half hh[4];
                hh[0] = __float2half_rn(silu_f(pc + pj.x + dd.x * wa + aa.x * wb));
                hh[1] = __float2half_rn(silu_f(pc + pj.y + dd.y * wa + aa.y * wb));
                hh[2] = __float2half_rn(silu_f(pc + pj.z + dd.z * wa + aa.z * wb));
                hh[3] = __float2half_rn(silu_f(pc + pj.w + dd.w * wa + aa.w * wb));
                *(uint2*)(uA0h + c * UPH + jq) = *(uint2*)hh;
            }
        }
        __syncthreads();

        float mi0 = 0.f, mi1 = 0.f;
        float ax = 0.f, ay = 0.f, az = 0.f;

        for (int tt = 0; tt < 4; tt++) {
            __half* uCur  = (tt & 1) ? uA1h : uA0h;
            __half* uNext = (tt & 1) ? uA0h : uA1h;

            // ---- P1: gemmB (+ x-accum(tt-1), geo prefetch) ----
            const bool pf = (tid < 128) && (tt + 1 < 4);
            float pd2 = 0.f, pa = 0.f;
            if (pf) {
                int jn = jbase0 + (tt + 1) * 128 + tid;
                float dx = xi0 - x[jn * 3 + 0];
                float dy = xi1 - x[jn * 3 + 1];
                float dz = xi2 - x[jn * 3 + 2];
                pd2 = dx * dx + dy * dy + dz * dz;
                pa = a[i * M_NODES + jn];
            }
            if (tt > 0 && tid < 128) {
                int jg = jbase0 + (tt - 1) * 128 + tid;
                float s = bx2v + redxp[tid] + redxp[132 + tid]
                               + redxp[264 + tid] + redxp[396 + tid];
                float dx = xi0 - x[jg * 3 + 0];
                float dy = xi1 - x[jg * 3 + 1];
                float dz = xi2 - x[jg * 3 + 2];
                ax += dx * s; ay += dy * s; az += dz * s;
            }

            gemmB(W2h, uCur, mTh, be2s, mi0, mi1, kw, jw, lane);

            if (pf) {
                float* gn = sm + OFF_GEOA + ((tt + 1) & 1) * 256;
                gn[tid] = pd2;
                gn[128 + tid] = pa;
            }
            __syncthreads();

            // ---- P2: gemmC + phase A(tt+1) ----
            gemmC(Wx1h, mTh, bx1s, wx2s, redxp, kw, jw, lane);

            if (tt + 1 < 4) {
                const float* geoA = sm + OFF_GEOA + ((tt + 1) & 1) * 256;
                const int j0 = jbase0 + (tt + 1) * 128;
                const int jq = lane * 4;
#pragma unroll
                for (int p = 0; p < 8; p++) {
                    int c = p * 8 + w;
                    float4 pj = *(const float4*)&g_pe_jT[c * M_NODES + j0 + jq];
                    float pc = peib[c], wa = w128s[c], wb = w129s[c];
                    float4 dd = *(const float4*)&geoA[jq];
                    float4 aa = *(const float4*)&geoA[128 + jq];
                    __half hh[4];
                    hh[0] = __float2half_rn(silu_f(pc + pj.x + dd.x * wa + aa.x * wb));
                    hh[1] = __float2half_rn(silu_f(pc + pj.y + dd.y * wa + aa.y * wb));
                    hh[2] = __float2half_rn(silu_f(pc + pj.z + dd.z * wa + aa.z * wb));
                    hh[3] = __float2half_rn(silu_f(pc + pj.w + dd.w * wa + aa.w * wb));
                    *(uint2*)(uNext + c * UPH + jq) = *(uint2*)hh;
                }
            }
            __syncthreads();
        }

        // x-accum for last tile of item
        if (tid < 128) {
            int jg = jbase0 + 3 * 128 + tid;
            float s = bx2v + redxp[tid] + redxp[132 + tid]
                           + redxp[264 + tid] + redxp[396 + tid];
            float dx = xi0 - x[jg * 3 + 0];
            float dy = xi1 - x[jg * 3 + 1];
            float dz = xi2 - x[jg * 3 + 2];
            ax += dx * s; ay += dy * s; az += dz * s;
        }

        // m_i lane-combine (lanes sharing same k-row)
        mi0 += __shfl_xor_sync(0xffffffff, mi0, 1);
        mi0 += __shfl_xor_sync(0xffffffff, mi0, 2);
        mi1 += __shfl_xor_sync(0xffffffff, mi1, 1);
        mi1 += __shfl_xor_sync(0xffffffff, mi1, 2);
        {
            const int q = lane >> 2, g = jw >> 6;
            if ((lane & 3) == 0) {
                redm[(kw + q) * 2 + g]     = mi0;
                redm[(kw + q + 8) * 2 + g] = mi1;
            }
        }
        if (tid < 128) { redx[tid] = ax; redx[128 + tid] = ay; redx[256 + tid] = az; }
        __syncthreads();

        if (tid < 64) g_mi[half][i][tid] = redm[tid * 2] + redm[tid * 2 + 1];
        if (tid >= 128 && tid < 131) {
            int comp = tid - 128;
            float s = 0.f;
            for (int q = 0; q < 128; q++) s += redx[comp * 128 + q];
            g_xp[half][i][comp] = s;
        }
        // no sync needed: next item's writes (peib/geo) don't alias redm/redx,
        // and their readers sit behind the next item-start __syncthreads()
    }
}

// finale: m_self correction, x output, phi_h. 4 nodes per 256-thr block.
__global__ void finale_kernel(
    const float* __restrict__ x, const float* __restrict__ a,
    const float* __restrict__ h,
    const float* __restrict__ We1, const float* __restrict__ be1,
    const float* __restrict__ be2,
    const float* __restrict__ Wh1, const float* __restrict__ bh1,
    const float* __restrict__ Wh2, const float* __restrict__ bh2,
    float* __restrict__ out)
{
    __shared__ float us[4][64], mi[4][64], gs[4][64];
    const int tid = threadIdx.x;
    const int sub = tid >> 6, k = tid & 63;
    const int i = blockIdx.x * 4 + sub;

    float a_ii = a[i * M_NODES + i];
    float pre = g_pe_i[i * 64 + k] + be1[k] + g_pe_jT[k * M_NODES + i]
              + a_ii * We1[129 * 64 + k];
    us[sub][k] = __half2float(__float2half_rn(silu_f(pre)));
    __syncthreads();

    float accd = be2[k];
#pragma unroll 8
    for (int c = 0; c < 64; c++)
        accd += us[sub][c] * __half2float(g_W2h[c * 64 + k]);
    float m_self = silu_f(accd);
    mi[sub][k] = g_mi[0][i][k] + g_mi[1][i][k] - m_self;

    if (k < 3) {
        const float C = 1.0f / (float)(M_NODES - 1);
        out[i * 3 + k] = x[i * 3 + k] + C * (g_xp[0][i][k] + g_xp[1][i][k]);
    }
    __syncthreads();

    float acc = bh1[k];
    const float* hr = h + i * 64;
#pragma unroll 4
    for (int c = 0; c < 64; c++) acc += hr[c] * Wh1[c * 64 + k];
#pragma unroll 4
    for (int c = 0; c < 64; c++) acc += mi[sub][c] * Wh1[(64 + c) * 64 + k];
    gs[sub][k] = silu_x(acc);
    __syncthreads();

    acc = bh2[k];
#pragma unroll 4
    for (int c = 0; c < 64; c++) acc += gs[sub][c] * Wh2[c * 64 + k];
    out[3 * M_NODES + i * 64 + k] = acc;
}

extern "C" void kernel_launch(void* const* d_in, const int* in_sizes, int n_in,
                              void* d_out, int out_size) {
    const float* x   = (const float*)d_in[0];
    const float* a   = (const float*)d_in[1];
    const float* h   = (const float*)d_in[2];
    const float* We1 = (const float*)d_in[3];
    const float* be1 = (const float*)d_in[4];
    const float* We2 = (const float*)d_in[5];
    const float* be2 = (const float*)d_in[6];
    const float* Wx1 = (const float*)d_in[7];
    const float* bx1 = (const float*)d_in[8];
    const float* Wx2 = (const float*)d_in[9];
    const float* bx2 = (const float*)d_in[10];
    const float* Wh1 = (const float*)d_in[11];
    const float* bh1 = (const float*)d_in[12];
    const float* Wh2 = (const float*)d_in[13];
    const float* bh2 = (const float*)d_in[14];
    float* out = (float*)d_out;

    cudaFuncSetAttribute(egnn_main, cudaFuncAttributeMaxDynamicSharedMemorySize, SMEM_BYTES);

    pe_kernel<<<(M_NODES * 64) / NTHREADS, NTHREADS>>>(h, We1, We2, Wx1);
    egnn_main<<<NCTAS, NTHREADS, SMEM_BYTES>>>(x, a, We1, be1, be2, bx1, Wx2, bx2);
    finale_kernel<<<M_NODES / 4, NTHREADS>>>(x, a, h, We1, be1, be2,
                                             Wh1, bh1, Wh2, bh2, out);
}

// round 12
// speedup vs baseline: 1.2928x; 1.0270x over previous
#include <cuda_runtime.h>
#include <cuda_fp16.h>
#include <mma.h>
using namespace nvcuda;

#define M_NODES 1024
#define UPH 72            // half-row stride for uA/mT (144B, mult of 16B)
#define NTHREADS 128
#define NCTAS 592         // persistent: 4 per SM on 148 SMs
#define NITEMS 4096       // (node i, j-quarter)

__device__ float g_pe_i[M_NODES * 64];
__device__ float g_pe_jT[64 * M_NODES];   // transposed: [c][j]
__device__ __half g_W2h[4096];
__device__ __half g_Wx1h[4096];
__device__ float g_mi[4][M_NODES][64];
__device__ float g_xp[4][M_NODES][4];

// fast silu: 0.5v(1+tanh(v/2)) — single MUFU.TANH
__device__ __forceinline__ float silu_f(float v) {
    float hv = 0.5f * v, t;
    asm("tanh.approx.f32 %0, %1;" : "=f"(t) : "f"(hv));
    return fmaf(hv, t, hv);
}
// exact silu for the final phi_h layer (direct output path)
__device__ __forceinline__ float silu_x(float v) {
    return v / (1.0f + __expf(-v));
}

__global__ void pe_kernel(const float* __restrict__ h, const float* __restrict__ We1,
                          const float* __restrict__ We2, const float* __restrict__ Wx1) {
    int id = blockIdx.x * blockDim.x + threadIdx.x;
    if (id < 4096) {
        g_W2h[id]  = __float2half_rn(We2[id]);
        g_Wx1h[id] = __float2half_rn(Wx1[id]);
    }
    int i = id >> 6, k = id & 63;
    const float* hr = h + i * 64;
    float a0 = 0.f, a1 = 0.f, b0 = 0.f, b1 = 0.f;
#pragma unroll
    for (int c = 0; c < 64; c += 2) {
        float h0 = hr[c], h1 = hr[c + 1];
        a0 += h0 * We1[c * 64 + k];
        b0 += h1 * We1[(c + 1) * 64 + k];
        a1 += h0 * We1[(64 + c) * 64 + k];
        b1 += h1 * We1[(65 + c) * 64 + k];
    }
    g_pe_i[id] = a0 + b0;
    g_pe_jT[k * M_NODES + i] = a1 + b1;
}

// SMEM layout (float offsets)
#define OFF_W2H   0         // 2048
#define OFF_WX1H  2048      // 2048
#define OFF_UA0   4096      // 64*72 halfs = 2304 fl
#define OFF_UA1   6400      // 2304
#define OFF_MTH   8704      // 2304
#define OFF_VEC   11008     // peib,w128,w129,wx2,be2,bx1 = 384
#define OFF_GEOA  11392     // 2*128 (d2 64 + a 64)
#define OFF_REDXP 11648     // 4*68 = 272
#define OFF_RED   11920     // redx 192
#define SMEM_FLOATS 12112
#define SMEM_BYTES (SMEM_FLOATS * 4)

// HMMA m16n16k16 fp32 accumulator mapping (sm_80+):
//   lane L: q=L>>2, p=L&3; element e: row = q + ((e&2)?8:0), col = 2p + (e&1) + ((e>=4)?8:0)
// 4 warps: warp w owns k-rows kw..kw+15 (kw = w*16); frag t covers j 16t..16t+15.

__device__ __forceinline__ void gemmB(const __half* __restrict__ W2h,
                                      const __half* __restrict__ uAh,
                                      __half* __restrict__ mTh,
                                      const float* __restrict__ be2s,
                                      float& mi0, float& mi1,
                                      int kw, int lane)
{
    wmma::fragment<wmma::accumulator, 16, 16, 16, float> cf[4];
#pragma unroll
    for (int t = 0; t < 4; t++) wmma::fill_fragment(cf[t], 0.0f);
    wmma::fragment<wmma::matrix_a, 16, 16, 16, __half, wmma::col_major> af;
    wmma::fragment<wmma::matrix_b, 16, 16, 16, __half, wmma::row_major> bf;
#pragma unroll
    for (int c0 = 0; c0 < 64; c0 += 16) {
        wmma::load_matrix_sync(af, W2h + kw + c0 * 64, 64);
#pragma unroll
        for (int t = 0; t < 4; t++) {
            wmma::load_matrix_sync(bf, uAh + c0 * UPH + 16 * t, UPH);
            wmma::mma_sync(cf[t], af, bf, cf[t]);
        }
    }
    const int q = lane >> 2, p = lane & 3;
    const int r0 = kw + q, r1 = r0 + 8;
    const float b0 = be2s[r0], b1 = be2s[r1];
#pragma unroll
    for (int t = 0; t < 4; t++) {
        float m0 = silu_f(cf[t].x[0] + b0), m1 = silu_f(cf[t].x[1] + b0);
        float m2 = silu_f(cf[t].x[2] + b1), m3 = silu_f(cf[t].x[3] + b1);
        float m4 = silu_f(cf[t].x[4] + b0), m5 = silu_f(cf[t].x[5] + b0);
        float m6 = silu_f(cf[t].x[6] + b1), m7 = silu_f(cf[t].x[7] + b1);
        mi0 += (m0 + m1) + (m4 + m5);
        mi1 += (m2 + m3) + (m6 + m7);
        __half2* d0 = (__half2*)(mTh + r0 * UPH + 16 * t + p * 2);
        __half2* d1 = (__half2*)(mTh + r1 * UPH + 16 * t + p * 2);
        d0[0] = __floats2half2_rn(m0, m1);
        d0[4] = __floats2half2_rn(m4, m5);
        d1[0] = __floats2half2_rn(m2, m3);
        d1[4] = __floats2half2_rn(m6, m7);
    }
}

__device__ __forceinline__ void gemmC(const __half* __restrict__ Wx1h,
                                      const __half* __restrict__ mTh,
                                      const float* __restrict__ bx1s,
                                      const float* __restrict__ wx2s,
                                      float* __restrict__ redxp,
                                      int kw, int lane)
{
    wmma::fragment<wmma::accumulator, 16, 16, 16, float> cf[4];
#pragma unroll
    for (int t = 0; t < 4; t++) wmma::fill_fragment(cf[t], 0.0f);
    wmma::fragment<wmma::matrix_a, 16, 16, 16, __half, wmma::col_major> af;
    wmma::fragment<wmma::matrix_b, 16, 16, 16, __half, wmma::row_major> bf;
#pragma unroll
    for (int c0 = 0; c0 < 64; c0 += 16) {
        wmma::load_matrix_sync(af, Wx1h + kw + c0 * 64, 64);
#pragma unroll
        for (int t = 0; t < 4; t++) {
            wmma::load_matrix_sync(bf, mTh + c0 * UPH + 16 * t, UPH);
            wmma::mma_sync(cf[t], af, bf, cf[t]);
        }
    }
    const int q = lane >> 2, p = lane & 3;
    const int r0 = kw + q, r1 = r0 + 8;
    const float ba = bx1s[r0], bb = bx1s[r1];
    const float wa = wx2s[r0], wb = wx2s[r1];
#pragma unroll
    for (int t = 0; t < 4; t++) {
        float s0 = silu_f(cf[t].x[0] + ba) * wa + silu_f(cf[t].x[2] + bb) * wb;
        float s1 = silu_f(cf[t].x[1] + ba) * wa + silu_f(cf[t].x[3] + bb) * wb;
        float s2 = silu_f(cf[t].x[4] + ba) * wa + silu_f(cf[t].x[6] + bb) * wb;
        float s3 = silu_f(cf[t].x[5] + ba) * wa + silu_f(cf[t].x[7] + bb) * wb;
#pragma unroll
        for (int msk = 4; msk <= 16; msk <<= 1) {
            s0 += __shfl_xor_sync(0xffffffff, s0, msk);
            s1 += __shfl_xor_sync(0xffffffff, s1, msk);
            s2 += __shfl_xor_sync(0xffffffff, s2, msk);
            s3 += __shfl_xor_sync(0xffffffff, s3, msk);
        }
        if (lane < 4) {
            float* rp = redxp + (kw >> 4) * 68 + 16 * t + p * 2;
            *(float2*)rp       = make_float2(s0, s1);
            *(float2*)(rp + 8) = make_float2(s2, s3);
        }
    }
}

__global__ void __launch_bounds__(NTHREADS, 4) egnn_main(
    const float* __restrict__ x, const float* __restrict__ a,
    const float* __restrict__ We1, const float* __restrict__ be1,
    const float* __restrict__ be2, const float* __restrict__ bx1,
    const float* __restrict__ Wx2, const float* __restrict__ bx2)
{
    extern __shared__ float sm[];
    __half* W2h  = (__half*)(sm + OFF_W2H);
    __half* Wx1h = (__half*)(sm + OFF_WX1H);
    __half* uA0h = (__half*)(sm + OFF_UA0);
    __half* uA1h = (__half*)(sm + OFF_UA1);
    __half* mTh  = (__half*)(sm + OFF_MTH);
    float* peib  = sm + OFF_VEC;
    float* w128s = peib + 64;
    float* w129s = w128s + 64;
    float* wx2s  = w129s + 64;
    float* be2s  = wx2s + 64;
    float* bx1s  = be2s + 64;
    float* redxp = sm + OFF_REDXP;
    float* redx  = sm + OFF_RED;      // [3][64]

    const int tid = threadIdx.x;
    const int lane = tid & 31;
    const int w = tid >> 5;           // 0..3
    const int kw = w * 16;

    // ---- one-time prologue: weights + layer vectors ----
    {
        const uint4* s2 = (const uint4*)g_W2h;
        const uint4* sx = (const uint4*)g_Wx1h;
        uint4* d2 = (uint4*)W2h;
        uint4* dx = (uint4*)Wx1h;
#pragma unroll
        for (int e = tid; e < 512; e += NTHREADS) { d2[e] = s2[e]; dx[e] = sx[e]; }
    }
    if (tid < 64) {
        w128s[tid] = We1[128 * 64 + tid];
        w129s[tid] = We1[129 * 64 + tid];
        wx2s[tid]  = Wx2[tid];
        be2s[tid]  = be2[tid];
        bx1s[tid]  = bx1[tid];
    }
    const float bx2v = bx2[0];

    for (int it = blockIdx.x; it < NITEMS; it += NCTAS) {
        const int i = it >> 2;
        const int quarter = it & 3;
        const int jbase0 = quarter * 256;
        const float xi0 = x[i * 3 + 0], xi1 = x[i * 3 + 1], xi2 = x[i * 3 + 2];

        // per-item: peib + geometry for first tile
        if (tid < 64) peib[tid] = g_pe_i[i * 64 + tid] + be1[tid];
        if (tid >= 64) {
            float* g0 = sm + OFF_GEOA;
            int j = tid - 64;
            int jn = jbase0 + j;
            float dx = xi0 - x[jn * 3 + 0];
            float dy = xi1 - x[jn * 3 + 1];
            float dz = xi2 - x[jn * 3 + 2];
            g0[j] = dx * dx + dy * dy + dz * dz;
            g0[64 + j] = a[i * M_NODES + jn];
        }
        __syncthreads();

        // initial phase A: u tile 0 (64c x 64j); thread handles 8c x 4j
        {
            const float* geoA = sm + OFF_GEOA;
            const int jq = (tid & 15) * 4;
            const int cb = tid >> 4;      // 0..7
#pragma unroll
            for (int p = 0; p < 8; p++) {
                int c = p * 8 + cb;
                float4 pj = *(const float4*)&g_pe_jT[c * M_NODES + jbase0 + jq];
                float pc = peib[c], wa = w128s[c], wb = w129s[c];
                float4 dd = *(const float4*)&geoA[jq];
                float4 aa = *(const float4*)&geoA[64 + jq];
                __half hh[4];
                hh[0] = __float2half_rn(silu_f(pc + pj.x + dd.x * wa + aa.x * wb));
                hh[1] = __float2half_rn(silu_f(pc + pj.y + dd.y * wa + aa.y * wb));
                hh[2] = __float2half_rn(silu_f(pc + pj.z + dd.z * wa + aa.z * wb));
                hh[3] = __float2half_rn(silu_f(pc + pj.w + dd.w * wa + aa.w * wb));
                *(uint2*)(uA0h + c * UPH + jq) = *(uint2*)hh;
            }
        }
        __syncthreads();

        float mi0 = 0.f, mi1 = 0.f;
        float ax = 0.f, ay = 0.f, az = 0.f;

        for (int tt = 0; tt < 4; tt++) {
            __half* uCur  = (tt & 1) ? uA1h : uA0h;
            __half* uNext = (tt & 1) ? uA0h : uA1h;

            // ---- P1: gemmB (+ x-accum(tt-1) on tid<64, geo prefetch on tid>=64) ----
            float pd2 = 0.f, pa = 0.f;
            const bool pf = (tid >= 64) && (tt + 1 < 4);
            if (pf) {
                int jn = jbase0 + (tt + 1) * 64 + (tid - 64);
                float dx = xi0 - x[jn * 3 + 0];
                float dy = xi1 - x[jn * 3 + 1];
                float dz = xi2 - x[jn * 3 + 2];
                pd2 = dx * dx + dy * dy + dz * dz;
                pa = a[i * M_NODES + jn];
            }
            if (tt > 0 && tid < 64) {
                int jg = jbase0 + (tt - 1) * 64 + tid;
                float s = bx2v + redxp[tid] + redxp[68 + tid]
                               + redxp[136 + tid] + redxp[204 + tid];
                float dx = xi0 - x[jg * 3 + 0];
                float dy = xi1 - x[jg * 3 + 1];
                float dz = xi2 - x[jg * 3 + 2];
                ax += dx * s; ay += dy * s; az += dz * s;
            }

            gemmB(W2h, uCur, mTh, be2s, mi0, mi1, kw, lane);

            if (pf) {
                float* gn = sm + OFF_GEOA + ((tt + 1) & 1) * 128;
                int j = tid - 64;
                gn[j] = pd2;
                gn[64 + j] = pa;
            }
            __syncthreads();

            // ---- P2: gemmC + phase A(tt+1) ----
            gemmC(Wx1h, mTh, bx1s, wx2s, redxp, kw, lane);

            if (tt + 1 < 4) {
                const float* geoA = sm + OFF_GEOA + ((tt + 1) & 1) * 128;
                const int j0 = jbase0 + (tt + 1) * 64;
                const int jq = (tid & 15) * 4;
                const int cb = tid >> 4;
#pragma unroll
                for (int p = 0; p < 8; p++) {
                    int c = p * 8 + cb;
                    float4 pj = *(const float4*)&g_pe_jT[c * M_NODES + j0 + jq];
                    float pc = peib[c], wa = w128s[c], wb = w129s[c];
                    float4 dd = *(const float4*)&geoA[jq];
                    float4 aa = *(const float4*)&geoA[64 + jq];
                    __half hh[4];
                    hh[0] = __float2half_rn(silu_f(pc + pj.x + dd.x * wa + aa.x * wb));
                    hh[1] = __float2half_rn(silu_f(pc + pj.y + dd.y * wa + aa.y * wb));
                    hh[2] = __float2half_rn(silu_f(pc + pj.z + dd.z * wa + aa.z * wb));
                    hh[3] = __float2half_rn(silu_f(pc + pj.w + dd.w * wa + aa.w * wb));
                    *(uint2*)(uNext + c * UPH + jq) = *(uint2*)hh;
                }
            }
            __syncthreads();
        }

        // x-accum for last tile of item
        if (tid < 64) {
            int jg = jbase0 + 3 * 64 + tid;
            float s = bx2v + redxp[tid] + redxp[68 + tid]
                           + redxp[136 + tid] + redxp[204 + tid];
            float dx = xi0 - x[jg * 3 + 0];
            float dy = xi1 - x[jg * 3 + 1];
            float dz = xi2 - x[jg * 3 + 2];
            ax += dx * s; ay += dy * s; az += dz * s;
        }

        // m_i: k-rows are warp-exclusive -> combine 4 lanes, write straight to global
        mi0 += __shfl_xor_sync(0xffffffff, mi0, 1);
        mi0 += __shfl_xor_sync(0xffffffff, mi0, 2);
        mi1 += __shfl_xor_sync(0xffffffff, mi1, 1);
        mi1 += __shfl_xor_sync(0xffffffff, mi1, 2);
        if ((lane & 3) == 0) {
            const int q = lane >> 2;
            g_mi[quarter][i][kw + q]     = mi0;
            g_mi[quarter][i][kw + q + 8] = mi1;
        }

        if (tid < 64) { redx[tid] = ax; redx[64 + tid] = ay; redx[128 + tid] = az; }
        __syncthreads();

        if (tid >= 64 && tid < 67) {
            int comp = tid - 64;
            float s = 0.f;
#pragma unroll 8
            for (int q = 0; q < 64; q++) s += redx[comp * 64 + q];
            g_xp[quarter][i][comp] = s;
        }
        __syncthreads();
    }
}

// finale: m_self correction, x output, phi_h. 4 nodes per 256-thr block.
__global__ void finale_kernel(
    const float* __restrict__ x, const float* __restrict__ a,
    const float* __restrict__ h,
    const float* __restrict__ We1, const float* __restrict__ be1,
    const float* __restrict__ be2,
    const float* __restrict__ Wh1, const float* __restrict__ bh1,
    const float* __restrict__ Wh2, const float* __restrict__ bh2,
    float* __restrict__ out)
{
    __shared__ float us[4][64], mi[4][64], gs[4][64];
    const int tid = threadIdx.x;
    const int sub = tid >> 6, k = tid & 63;
    const int i = blockIdx.x * 4 + sub;

    float a_ii = a[i * M_NODES + i];
    float pre = g_pe_i[i * 64 + k] + be1[k] + g_pe_jT[k * M_NODES + i]
              + a_ii * We1[129 * 64 + k];
    us[sub][k] = __half2float(__float2half_rn(silu_f(pre)));
    __syncthreads();

    float accd = be2[k];
#pragma unroll 8
    for (int c = 0; c < 64; c++)
        accd += us[sub][c] * __half2float(g_W2h[c * 64 + k]);
    float m_self = silu_f(accd);
    mi[sub][k] = ((g_mi[0][i][k] + g_mi[1][i][k])
                + (g_mi[2][i][k] + g_mi[3][i][k])) - m_self;

    if (k < 3) {
        const float C = 1.0f / (float)(M_NODES - 1);
        float s = (g_xp[0][i][k] + g_xp[1][i][k]) + (g_xp[2][i][k] + g_xp[3][i][k]);
        out[i * 3 + k] = x[i * 3 + k] + C * s;
    }
    __syncthreads();

    float acc = bh1[k];
    const float* hr = h + i * 64;
#pragma unroll 4
    for (int c = 0; c < 64; c++) acc += hr[c] * Wh1[c * 64 + k];
#pragma unroll 4
    for (int c = 0; c < 64; c++) acc += mi[sub][c] * Wh1[(64 + c) * 64 + k];
    gs[sub][k] = silu_x(acc);
    __syncthreads();

    acc = bh2[k];
#pragma unroll 4
    for (int c = 0; c < 64; c++) acc += gs[sub][c] * Wh2[c * 64 + k];
    out[3 * M_NODES + i * 64 + k] = acc;
}

extern "C" void kernel_launch(void* const* d_in, const int* in_sizes, int n_in,
                              void* d_out, int out_size) {
    const float* x   = (const float*)d_in[0];
    const float* a   = (const float*)d_in[1];
    const float* h   = (const float*)d_in[2];
    const float* We1 = (const float*)d_in[3];
    const float* be1 = (const float*)d_in[4];
    const float* We2 = (const float*)d_in[5];
    const float* be2 = (const float*)d_in[6];
    const float* Wx1 = (const float*)d_in[7];
    const float* bx1 = (const float*)d_in[8];
    const float* Wx2 = (const float*)d_in[9];
    const float* bx2 = (const float*)d_in[10];
    const float* Wh1 = (const float*)d_in[11];
    const float* bh1 = (const float*)d_in[12];
    const float* Wh2 = (const float*)d_in[13];
    const float* bh2 = (const float*)d_in[14];
    float* out = (float*)d_out;

    cudaFuncSetAttribute(egnn_main, cudaFuncAttributeMaxDynamicSharedMemorySize, SMEM_BYTES);

    pe_kernel<<<(M_NODES * 64) / 256, 256>>>(h, We1, We2, Wx1);
    egnn_main<<<NCTAS, NTHREADS, SMEM_BYTES>>>(x, a, We1, be1, be2, bx1, Wx2, bx2);
    finale_kernel<<<M_NODES / 4, 256>>>(x, a, h, We1, be1, be2,
                                        Wh1, bh1, Wh2, bh2, out);
}

// round 14
// speedup vs baseline: 1.3503x; 1.0445x over previous
#include <cuda_runtime.h>
#include <cuda_fp16.h>
#include <mma.h>
using namespace nvcuda;

#define M_NODES 1024
#define UPH 72            // half-row stride for uA/mT (144B, mult of 16B)
#define NTHREADS 128
#define NCTAS 740         // persistent: 5 per SM on 148 SMs
#define NITEMS 4096       // (node i, j-quarter)

__device__ float g_pe_i[M_NODES * 64];
__device__ float g_pe_jT[64 * M_NODES];   // transposed: [c][j]
__device__ __half g_W2h[4096];
__device__ __half g_Wx1h[4096];
__device__ float g_mi[4][M_NODES][64];
__device__ float g_xp[4][M_NODES][4];

// fast silu: 0.5v(1+tanh(v/2)) — single MUFU.TANH
__device__ __forceinline__ float silu_f(float v) {
    float hv = 0.5f * v, t;
    asm("tanh.approx.f32 %0, %1;" : "=f"(t) : "f"(hv));
    return fmaf(hv, t, hv);
}
// exact silu for the final phi_h layer (direct output path)
__device__ __forceinline__ float silu_x(float v) {
    return v / (1.0f + __expf(-v));
}

__global__ void pe_kernel(const float* __restrict__ h, const float* __restrict__ We1,
                          const float* __restrict__ We2, const float* __restrict__ Wx1) {
    int id = blockIdx.x * blockDim.x + threadIdx.x;
    if (id < 4096) {
        g_W2h[id]  = __float2half_rn(We2[id]);
        g_Wx1h[id] = __float2half_rn(Wx1[id]);
    }
    int i = id >> 6, k = id & 63;
    const float* hr = h + i * 64;
    float a0 = 0.f, a1 = 0.f, b0 = 0.f, b1 = 0.f;
    float c0 = 0.f, c1 = 0.f, d0 = 0.f, d1 = 0.f;
#pragma unroll
    for (int c = 0; c < 64; c += 4) {
        float h0 = hr[c], h1 = hr[c + 1], h2 = hr[c + 2], h3 = hr[c + 3];
        a0 += h0 * We1[c * 64 + k];
        b0 += h1 * We1[(c + 1) * 64 + k];
        c0 += h2 * We1[(c + 2) * 64 + k];
        d0 += h3 * We1[(c + 3) * 64 + k];
        a1 += h0 * We1[(64 + c) * 64 + k];
        b1 += h1 * We1[(65 + c) * 64 + k];
        c1 += h2 * We1[(66 + c) * 64 + k];
        d1 += h3 * We1[(67 + c) * 64 + k];
    }
    g_pe_i[id] = (a0 + b0) + (c0 + d0);
    g_pe_jT[k * M_NODES + i] = (a1 + b1) + (c1 + d1);
}

// SMEM layout (float offsets) — single u buffer (u(t) dies in P1, u(t+1) written in P2)
#define OFF_W2H   0         // 2048
#define OFF_WX1H  2048      // 2048
#define OFF_UA    4096      // 64*72 halfs = 2304 fl (redx aliases here at item end)
#define OFF_MTH   6400      // 2304
#define OFF_VEC   8704      // peib,w128,w129,wx2,be2,bx1 = 384
#define OFF_GEOA  9088      // 2*128 (d2 64 + a 64)
#define OFF_REDXP 9344      // 4*68 = 272
#define SMEM_FLOATS 9616
#define SMEM_BYTES (SMEM_FLOATS * 4)   // 38464 B -> 5 CTAs/SM

// HMMA m16n16k16 fp32 accumulator mapping (sm_80+):
//   lane L: q=L>>2, p=L&3; element e: row = q + ((e&2)?8:0), col = 2p + (e&1) + ((e>=4)?8:0)
// 4 warps: warp w owns k-rows kw..kw+15 (kw = w*16); frag t covers j 16t..16t+15.

__device__ __forceinline__ void gemmB(const __half* __restrict__ W2h,
                                      const __half* __restrict__ uAh,
                                      __half* __restrict__ mTh,
                                      const float* __restrict__ be2s,
                                      float& mi0, float& mi1,
                                      int kw, int lane)
{
    wmma::fragment<wmma::accumulator, 16, 16, 16, float> cf[4];
#pragma unroll
    for (int t = 0; t < 4; t++) wmma::fill_fragment(cf[t], 0.0f);
    wmma::fragment<wmma::matrix_a, 16, 16, 16, __half, wmma::col_major> af;
    wmma::fragment<wmma::matrix_b, 16, 16, 16, __half, wmma::row_major> bf;
#pragma unroll
    for (int c0 = 0; c0 < 64; c0 += 16) {
        wmma::load_matrix_sync(af, W2h + kw + c0 * 64, 64);
#pragma unroll
        for (int t = 0; t < 4; t++) {
            wmma::load_matrix_sync(bf, uAh + c0 * UPH + 16 * t, UPH);
            wmma::mma_sync(cf[t], af, bf, cf[t]);
        }
    }
    const int q = lane >> 2, p = lane & 3;
    const int r0 = kw + q, r1 = r0 + 8;
    const float b0 = be2s[r0], b1 = be2s[r1];
#pragma unroll
    for (int t = 0; t < 4; t++) {
        float m0 = silu_f(cf[t].x[0] + b0), m1 = silu_f(cf[t].x[1] + b0);
        float m2 = silu_f(cf[t].x[2] + b1), m3 = silu_f(cf[t].x[3] + b1);
        float m4 = silu_f(cf[t].x[4] + b0), m5 = silu_f(cf[t].x[5] + b0);
        float m6 = silu_f(cf[t].x[6] + b1), m7 = silu_f(cf[t].x[7] + b1);
        mi0 += (m0 + m1) + (m4 + m5);
        mi1 += (m2 + m3) + (m6 + m7);
        __half2* d0 = (__half2*)(mTh + r0 * UPH + 16 * t + p * 2);
        __half2* d1 = (__half2*)(mTh + r1 * UPH + 16 * t + p * 2);
        d0[0] = __floats2half2_rn(m0, m1);
        d0[4] = __floats2half2_rn(m4, m5);
        d1[0] = __floats2half2_rn(m2, m3);
        d1[4] = __floats2half2_rn(m6, m7);
    }
}

__device__ __forceinline__ void gemmC(const __half* __restrict__ Wx1h,
                                      const __half* __restrict__ mTh,
                                      const float* __restrict__ bx1s,
                                      const float* __restrict__ wx2s,
                                      float* __restrict__ redxp,
                                      int kw, int lane)
{
    wmma::fragment<wmma::accumulator, 16, 16, 16, float> cf[4];
#pragma unroll
    for (int t = 0; t < 4; t++) wmma::fill_fragment(cf[t], 0.0f);
    wmma::fragment<wmma::matrix_a, 16, 16, 16, __half, wmma::col_major> af;
    wmma::fragment<wmma::matrix_b, 16, 16, 16, __half, wmma::row_major> bf;
#pragma unroll
    for (int c0 = 0; c0 < 64; c0 += 16) {
        wmma::load_matrix_sync(af, Wx1h + kw + c0 * 64, 64);
#pragma unroll
        for (int t = 0; t < 4; t++) {
            wmma::load_matrix_sync(bf, mTh + c0 * UPH + 16 * t, UPH);
            wmma::mma_sync(cf[t], af, bf, cf[t]);
        }
    }
    const int q = lane >> 2, p = lane & 3;
    const int r0 = kw + q, r1 = r0 + 8;
    const float ba = bx1s[r0], bb = bx1s[r1];
    const float wa = wx2s[r0], wb = wx2s[r1];
#pragma unroll
    for (int t = 0; t < 4; t++) {
        float s0 = silu_f(cf[t].x[0] + ba) * wa + silu_f(cf[t].x[2] + bb) * wb;
        float s1 = silu_f(cf[t].x[1] + ba) * wa + silu_f(cf[t].x[3] + bb) * wb;
        float s2 = silu_f(cf[t].x[4] + ba) * wa + silu_f(cf[t].x[6] + bb) * wb;
        float s3 = silu_f(cf[t].x[5] + ba) * wa + silu_f(cf[t].x[7] + bb) * wb;
#pragma unroll
        for (int msk = 4; msk <= 16; msk <<= 1) {
            s0 += __shfl_xor_sync(0xffffffff, s0, msk);
            s1 += __shfl_xor_sync(0xffffffff, s1, msk);
            s2 += __shfl_xor_sync(0xffffffff, s2, msk);
            s3 += __shfl_xor_sync(0xffffffff, s3, msk);
        }
        if (lane < 4) {
            float* rp = redxp + (kw >> 4) * 68 + 16 * t + p * 2;
            *(float2*)rp       = make_float2(s0, s1);
            *(float2*)(rp + 8) = make_float2(s2, s3);
        }
    }
}

__global__ void __launch_bounds__(NTHREADS, 5) egnn_main(
    const float* __restrict__ x, const float* __restrict__ a,
    const float* __restrict__ We1, const float* __restrict__ be1,
    const float* __restrict__ be2, const float* __restrict__ bx1,
    const float* __restrict__ Wx2, const float* __restrict__ bx2)
{
    extern __shared__ float sm[];
    __half* W2h  = (__half*)(sm + OFF_W2H);
    __half* Wx1h = (__half*)(sm + OFF_WX1H);
    __half* uAh  = (__half*)(sm + OFF_UA);
    __half* mTh  = (__half*)(sm + OFF_MTH);
    float* peib  = sm + OFF_VEC;
    float* w128s = peib + 64;
    float* w129s = w128s + 64;
    float* wx2s  = w129s + 64;
    float* be2s  = wx2s + 64;
    float* bx1s  = be2s + 64;
    float* redxp = sm + OFF_REDXP;
    float* redx  = sm + OFF_UA;       // alias: uA dead at item end

    const int tid = threadIdx.x;
    const int lane = tid & 31;
    const int w = tid >> 5;           // 0..3
    const int kw = w * 16;

    // ---- one-time prologue: weights + layer vectors ----
    {
        const uint4* s2 = (const uint4*)g_W2h;
        const uint4* sx = (const uint4*)g_Wx1h;
        uint4* d2 = (uint4*)W2h;
        uint4* dx = (uint4*)Wx1h;
#pragma unroll
        for (int e = tid; e < 512; e += NTHREADS) { d2[e] = s2[e]; dx[e] = sx[e]; }
    }
    if (tid < 64) {
        w128s[tid] = We1[128 * 64 + tid];
        w129s[tid] = We1[129 * 64 + tid];
        wx2s[tid]  = Wx2[tid];
        be2s[tid]  = be2[tid];
        bx1s[tid]  = bx1[tid];
    }
    const float bx2v = bx2[0];

    for (int it = blockIdx.x; it < NITEMS; it += NCTAS) {
        const int i = it >> 2;
        const int quarter = it & 3;
        const int jbase0 = quarter * 256;
        const float xi0 = x[i * 3 + 0], xi1 = x[i * 3 + 1], xi2 = x[i * 3 + 2];

        // per-item: peib + geometry for first tile
        if (tid < 64) peib[tid] = g_pe_i[i * 64 + tid] + be1[tid];
        if (tid >= 64) {
            float* g0 = sm + OFF_GEOA;
            int j = tid - 64;
            int jn = jbase0 + j;
            float dx = xi0 - x[jn * 3 + 0];
            float dy = xi1 - x[jn * 3 + 1];
            float dz = xi2 - x[jn * 3 + 2];
            g0[j] = dx * dx + dy * dy + dz * dz;
            g0[64 + j] = a[i * M_NODES + jn];
        }
        __syncthreads();

        // initial phase A: u tile 0 (64c x 64j); thread handles 8c x 4j
        {
            const float* geoA = sm + OFF_GEOA;
            const int jq = (tid & 15) * 4;
            const int cb = tid >> 4;      // 0..7
#pragma unroll
            for (int p = 0; p < 8; p++) {
                int c = p * 8 + cb;
                float4 pj = *(const float4*)&g_pe_jT[c * M_NODES + jbase0 + jq];
                float pc = peib[c], wa = w128s[c], wb = w129s[c];
                float4 dd = *(const float4*)&geoA[jq];
                float4 aa = *(const float4*)&geoA[64 + jq];
                __half hh[4];
                hh[0] = __float2half_rn(silu_f(pc + pj.x + dd.x * wa + aa.x * wb));
                hh[1] = __float2half_rn(silu_f(pc + pj.y + dd.y * wa + aa.y * wb));
                hh[2] = __float2half_rn(silu_f(pc + pj.z + dd.z * wa + aa.z * wb));
                hh[3] = __float2half_rn(silu_f(pc + pj.w + dd.w * wa + aa.w * wb));
                *(uint2*)(uAh + c * UPH + jq) = *(uint2*)hh;
            }
        }
        __syncthreads();

        float mi0 = 0.f, mi1 = 0.f;
        float ax = 0.f, ay = 0.f, az = 0.f;

        for (int tt = 0; tt < 4; tt++) {
            // ---- P1: gemmB reads uA (+ x-accum(tt-1) tid<64, geo prefetch tid>=64) ----
            float pd2 = 0.f, pa = 0.f;
            const bool pf = (tid >= 64) && (tt + 1 < 4);
            if (pf) {
                int jn = jbase0 + (tt + 1) * 64 + (tid - 64);
                float dx = xi0 - x[jn * 3 + 0];
                float dy = xi1 - x[jn * 3 + 1];
                float dz = xi2 - x[jn * 3 + 2];
                pd2 = dx * dx + dy * dy + dz * dz;
                pa = a[i * M_NODES + jn];
            }
            if (tt > 0 && tid < 64) {
                int jg = jbase0 + (tt - 1) * 64 + tid;
                float s = bx2v + redxp[tid] + redxp[68 + tid]
                               + redxp[136 + tid] + redxp[204 + tid];
                float dx = xi0 - x[jg * 3 + 0];
                float dy = xi1 - x[jg * 3 + 1];
                float dz = xi2 - x[jg * 3 + 2];
                ax += dx * s; ay += dy * s; az += dz * s;
            }

            gemmB(W2h, uAh, mTh, be2s, mi0, mi1, kw, lane);

            if (pf) {
                float* gn = sm + OFF_GEOA + ((tt + 1) & 1) * 128;
                int j = tid - 64;
                gn[j] = pd2;
                gn[64 + j] = pa;
            }
            __syncthreads();

            // ---- P2: gemmC + phase A(tt+1) overwrites uA (dead after P1) ----
            gemmC(Wx1h, mTh, bx1s, wx2s, redxp, kw, lane);

            if (tt + 1 < 4) {
                const float* geoA = sm + OFF_GEOA + ((tt + 1) & 1) * 128;
                const int j0 = jbase0 + (tt + 1) * 64;
                const int jq = (tid & 15) * 4;
                const int cb = tid >> 4;
#pragma unroll
                for (int p = 0; p < 8; p++) {
                    int c = p * 8 + cb;
                    float4 pj = *(const float4*)&g_pe_jT[c * M_NODES + j0 + jq];
                    float pc = peib[c], wa = w128s[c], wb = w129s[c];
                    float4 dd = *(const float4*)&geoA[jq];
                    float4 aa = *(const float4*)&geoA[64 + jq];
                    __half hh[4];
                    hh[0] = __float2half_rn(silu_f(pc + pj.x + dd.x * wa + aa.x * wb));
                    hh[1] = __float2half_rn(silu_f(pc + pj.y + dd.y * wa + aa.y * wb));
                    hh[2] = __float2half_rn(silu_f(pc + pj.z + dd.z * wa + aa.z * wb));
                    hh[3] = __float2half_rn(silu_f(pc + pj.w + dd.w * wa + aa.w * wb));
                    *(uint2*)(uAh + c * UPH + jq) = *(uint2*)hh;
                }
            }
            __syncthreads();
        }

        // x-accum for last tile of item
        if (tid < 64) {
            int jg = jbase0 + 3 * 64 + tid;
            float s = bx2v + redxp[tid] + redxp[68 + tid]
                           + redxp[136 + tid] + redxp[204 + tid];
            float dx = xi0 - x[jg * 3 + 0];
            float dy = xi1 - x[jg * 3 + 1];
            float dz = xi2 - x[jg * 3 + 2];
            ax += dx * s; ay += dy * s; az += dz * s;
        }

        // m_i: k-rows are warp-exclusive -> combine 4 lanes, write straight to global
        mi0 += __shfl_xor_sync(0xffffffff, mi0, 1);
        mi0 += __shfl_xor_sync(0xffffffff, mi0, 2);
        mi1 += __shfl_xor_sync(0xffffffff, mi1, 1);
        mi1 += __shfl_xor_sync(0xffffffff, mi1, 2);
        if ((lane & 3) == 0) {
            const int q = lane >> 2;
            g_mi[quarter][i][kw + q]     = mi0;
            g_mi[quarter][i][kw + q + 8] = mi1;
        }

        __syncthreads();   // uA (redx alias) dead: all gemmB reads done
        if (tid < 64) { redx[tid] = ax; redx[64 + tid] = ay; redx[128 + tid] = az; }
        __syncthreads();

        if (tid >= 64 && tid < 67) {
            int comp = tid - 64;
            float s = 0.f;
#pragma unroll 8
            for (int q = 0; q < 64; q++) s += redx[comp * 64 + q];
            g_xp[quarter][i][comp] = s;
        }
        __syncthreads();
    }
}

// finale: m_self correction, x output, phi_h. 4 nodes per 256-thr block.
__global__ void finale_kernel(
    const float* __restrict__ x, const float* __restrict__ a,
    const float* __restrict__ h,
    const float* __restrict__ We1, const float* __restrict__ be1,
    const float* __restrict__ be2,
    const float* __restrict__ Wh1, const float* __restrict__ bh1,
    const float* __restrict__ Wh2, const float* __restrict__ bh2,
    float* __restrict__ out)
{
    __shared__ float us[4][64], mi[4][64], gs[4][64];
    const int tid = threadIdx.x;
    const int sub = tid >> 6, k = tid & 63;
    const int i = blockIdx.x * 4 + sub;

    float a_ii = a[i * M_NODES + i];
    float pre = g_pe_i[i * 64 + k] + be1[k] + g_pe_jT[k * M_NODES + i]
              + a_ii * We1[129 * 64 + k];
    us[sub][k] = __half2float(__float2half_rn(silu_f(pre)));
    __syncthreads();

    float accd = be2[k];
#pragma unroll 8
    for (int c = 0; c < 64; c++)
        accd += us[sub][c] * __half2float(g_W2h[c * 64 + k]);
    float m_self = silu_f(accd);
    mi[sub][k] = ((g_mi[0][i][k] + g_mi[1][i][k])
                + (g_mi[2][i][k] + g_mi[3][i][k])) - m_self;

    if (k < 3) {
        const float C = 1.0f / (float)(M_NODES - 1);
        float s = (g_xp[0][i][k] + g_xp[1][i][k]) + (g_xp[2][i][k] + g_xp[3][i][k]);
        out[i * 3 + k] = x[i * 3 + k] + C * s;
    }
    __syncthreads();

    float acc = bh1[k];
    const float* hr = h + i * 64;
#pragma unroll 4
    for (int c = 0; c < 64; c++) acc += hr[c] * Wh1[c * 64 + k];
#pragma unroll 4
    for (int c = 0; c < 64; c++) acc += mi[sub][c] * Wh1[(64 + c) * 64 + k];
    gs[sub][k] = silu_x(acc);
    __syncthreads();

    acc = bh2[k];
#pragma unroll 4
    for (int c = 0; c < 64; c++) acc += gs[sub][c] * Wh2[c * 64 + k];
    out[3 * M_NODES + i * 64 + k] = acc;
}

extern "C" void kernel_launch(void* const* d_in, const int* in_sizes, int n_in,
                              void* d_out, int out_size) {
    const float* x   = (const float*)d_in[0];
    const float* a   = (const float*)d_in[1];
    const float* h   = (const float*)d_in[2];
    const float* We1 = (const float*)d_in[3];
    const float* be1 = (const float*)d_in[4];
    const float* We2 = (const float*)d_in[5];
    const float* be2 = (const float*)d_in[6];
    const float* Wx1 = (const float*)d_in[7];
    const float* bx1 = (const float*)d_in[8];
    const float* Wx2 = (const float*)d_in[9];
    const float* bx2 = (const float*)d_in[10];
    const float* Wh1 = (const float*)d_in[11];
    const float* bh1 = (const float*)d_in[12];
    const float* Wh2 = (const float*)d_in[13];
    const float* bh2 = (const float*)d_in[14];
    float* out = (float*)d_out;

    cudaFuncSetAttribute(egnn_main, cudaFuncAttributeMaxDynamicSharedMemorySize, SMEM_BYTES);

    pe_kernel<<<(M_NODES * 64) / 256, 256>>>(h, We1, We2, Wx1);
    egnn_main<<<NCTAS, NTHREADS, SMEM_BYTES>>>(x, a, We1, be1, be2, bx1, Wx2, bx2);
    finale_kernel<<<M_NODES / 4, 256>>>(x, a, h, We1, be1, be2,
                                        Wh1, bh1, Wh2, bh2, out);
}